// round 12
// baseline (speedup 1.0000x reference)
#include <cuda_runtime.h>
#include <cstdint>

// Problem constants (match reference init_kwargs)
static constexpr int H = 1080;
static constexpr int W = 1920;
static constexpr int NPIX = H * W;           // 2,073,600 = 8100 * 256
static constexpr float ZNEAR = 0.2f;
static constexpr float SH_C0 = 0.28209479177387814f;

// Scratch z-buffer holding COMPLEMENTED keys, resolved by atomicMax.
//   stored = ~((depth_bits << 32) | idx), miss sentinel = 0.
// Invariant: all-zero at the start of every kernel_launch call.
//   - zero-initialized at module load (first call)
//   - re-zeroed by clear_kernel at the END of every call (PDL-overlapped
//     with resolve's store drain, so it is off the critical path).
__device__ unsigned long long g_zbuf[NPIX];

// PDL intrinsics (sm_90+)
__device__ __forceinline__ void pdl_wait() {
    asm volatile("griddepcontrol.wait;" ::: "memory");
}
__device__ __forceinline__ void pdl_trigger() {
    asm volatile("griddepcontrol.launch_dependents;" ::: "memory");
}

// ---------------------------------------------------------------------------
// Project one point: bit-exact per-op float32 (no FMA fusion).
// ---------------------------------------------------------------------------
struct Mats {
    float P00, P10, P20, P30;
    float P01, P11, P21, P31;
    float P03, P13, P23, P33;
    float V02, V12, V22, V32;
};

__device__ __forceinline__ void project_one(float x, float y, float z, int i,
                                            const Mats& M) {
    float phx = __fadd_rn(__fadd_rn(__fmul_rn(x, M.P00), __fmul_rn(y, M.P10)),
                          __fadd_rn(__fmul_rn(z, M.P20), M.P30));
    float phy = __fadd_rn(__fadd_rn(__fmul_rn(x, M.P01), __fmul_rn(y, M.P11)),
                          __fadd_rn(__fmul_rn(z, M.P21), M.P31));
    float phw = __fadd_rn(__fadd_rn(__fmul_rn(x, M.P03), __fmul_rn(y, M.P13)),
                          __fadd_rn(__fmul_rn(z, M.P23), M.P33));

    float inv_w = __fdiv_rn(1.0f, __fadd_rn(phw, 1e-7f));

    float depth = __fadd_rn(__fadd_rn(__fmul_rn(x, M.V02), __fmul_rn(y, M.V12)),
                            __fadd_rn(__fmul_rn(z, M.V22), M.V32));

    float ndcx = __fmul_rn(phx, inv_w);
    float ndcy = __fmul_rn(phy, inv_w);
    float fx = __fsub_rn(__fmul_rn(__fmul_rn(__fadd_rn(ndcx, 1.0f),
                                             (float)W), 0.5f), 0.5f);
    float fy = __fsub_rn(__fmul_rn(__fmul_rn(__fadd_rn(ndcy, 1.0f),
                                             (float)H), 0.5f), 0.5f);

    if (!(depth > ZNEAR)) return;
    if (!(fx > -2.0f && fx < (float)(W + 1) &&
          fy > -2.0f && fy < (float)(H + 1))) return;
    int px = (int)rintf(fx);
    int py = (int)rintf(fy);
    if (px < 0 || px >= W || py < 0 || py >= H) return;

    unsigned long long key =
        ((unsigned long long)__float_as_uint(depth) << 32) | (unsigned)i;
    atomicMax(&g_zbuf[py * W + px], ~key);
}

__device__ __forceinline__ Mats load_mats(const float* __restrict__ viewmatrix,
                                          const float* __restrict__ projmatrix) {
    Mats M;
    M.P00 = __ldg(&projmatrix[0]);  M.P10 = __ldg(&projmatrix[4]);
    M.P20 = __ldg(&projmatrix[8]);  M.P30 = __ldg(&projmatrix[12]);
    M.P01 = __ldg(&projmatrix[1]);  M.P11 = __ldg(&projmatrix[5]);
    M.P21 = __ldg(&projmatrix[9]);  M.P31 = __ldg(&projmatrix[13]);
    M.P03 = __ldg(&projmatrix[3]);  M.P13 = __ldg(&projmatrix[7]);
    M.P23 = __ldg(&projmatrix[11]); M.P33 = __ldg(&projmatrix[15]);
    M.V02 = __ldg(&viewmatrix[2]);  M.V12 = __ldg(&viewmatrix[6]);
    M.V22 = __ldg(&viewmatrix[10]); M.V32 = __ldg(&viewmatrix[14]);
    return M;
}

// ---------------------------------------------------------------------------
// Pass 1: 4 points per thread; three float4 loads. Tail per-element.
// ---------------------------------------------------------------------------
__global__ void project_kernel(const float* __restrict__ means3D,
                               const float* __restrict__ viewmatrix,
                               const float* __restrict__ projmatrix,
                               int n) {
    int t = blockIdx.x * blockDim.x + threadIdx.x;
    int i0 = 4 * t;
    if (i0 >= n) { pdl_trigger(); return; }

    Mats M = load_mats(viewmatrix, projmatrix);

    if (i0 + 4 <= n) {
        const float4* __restrict__ m4 =
            reinterpret_cast<const float4*>(means3D + 12 * (size_t)t);
        float4 a = __ldg(&m4[0]);   // x0 y0 z0 x1
        float4 b = __ldg(&m4[1]);   // y1 z1 x2 y2
        float4 c = __ldg(&m4[2]);   // z2 x3 y3 z3
        project_one(a.x, a.y, a.z, i0 + 0, M);
        project_one(a.w, b.x, b.y, i0 + 1, M);
        project_one(b.z, b.w, c.x, i0 + 2, M);
        project_one(c.y, c.z, c.w, i0 + 3, M);
    } else {
        for (int i = i0; i < n; i++) {
            float x = means3D[3 * i + 0];
            float y = means3D[3 * i + 1];
            float z = means3D[3 * i + 2];
            project_one(x, y, z, i, M);
        }
    }
    pdl_trigger();                  // this CTA's zbuf updates are issued
}

// ---------------------------------------------------------------------------
// Pass 2: resolve. One block = 256 consecutive pixels (NPIX = 8100*256).
// zbuf READ-ONLY; reads it once at the top, then triggers the clear kernel
// (WAR-safe: trigger is after all this CTA's zbuf reads are consumed).
// out layout (floats): idx[NPIX] | col[NPIX*3] | depth[NPIX] | feat[NPIX*32]
// ---------------------------------------------------------------------------
__global__ __launch_bounds__(256) void resolve_kernel(
        const float* __restrict__ shs,        // stride 48 floats
        const float* __restrict__ feat,       // stride 32 floats
        const float* __restrict__ bg,
        float* __restrict__ out, int n) {
    __shared__ unsigned s_idx[256];
    __shared__ unsigned s_dep[256];

    int t = threadIdx.x;
    int p0 = blockIdx.x * 256;

    float* __restrict__ o_idx  = out;
    float* __restrict__ o_col  = out + (size_t)NPIX;
    float* __restrict__ o_dep  = out + (size_t)4 * NPIX;
    float* __restrict__ o_feat = out + (size_t)5 * NPIX;

    pdl_wait();                     // project's zbuf writes must be visible

    // Keys: 2 pixels per thread via 16B loads (first 128 threads cover 256).
    if (t < 128) {
        ulonglong2 st = __ldg(reinterpret_cast<const ulonglong2*>(
                                  &g_zbuf[p0]) + t);
        #pragma unroll
        for (int k = 0; k < 2; k++) {
            unsigned long long stored = k ? st.y : st.x;
            unsigned long long key = ~stored;
            unsigned idx = (unsigned)(key & 0xFFFFFFFFull);
            bool hit = (stored != 0ULL) && (idx < (unsigned)n);
            s_idx[2 * t + k] = hit ? idx : 0xFFFFFFFFu;
            s_dep[2 * t + k] = hit ? (unsigned)(key >> 32) : 0u;
        }
    }
    __syncthreads();
    pdl_trigger();                  // zbuf fully consumed -> clear may start

    {
        unsigned id = s_idx[t];
        bool hit = id != 0xFFFFFFFFu;
        o_idx[p0 + t] = hit ? (float)id : -1.0f;
        o_dep[p0 + t] = __uint_as_float(s_dep[t]);
    }

    // Features: batch all 8 gather loads (independent, in flight together),
    // then all 8 coalesced stores. 8 threads per pixel, one float4 chunk.
    int pix_in_round = t >> 3;        // 0..31
    int chunk = t & 7;                // 0..7
    float4 fv[8];
    #pragma unroll
    for (int r = 0; r < 8; r++) {
        int pix = r * 32 + pix_in_round;      // 0..255
        unsigned id2 = s_idx[pix];
        fv[r] = (id2 != 0xFFFFFFFFu)
            ? __ldg(&reinterpret_cast<const float4*>(
                        feat + (size_t)id2 * 32)[chunk])
            : make_float4(0.f, 0.f, 0.f, 0.f);
    }

    // Color: 3 rounds of 256 contiguous floats (overlaps with feat loads).
    #pragma unroll
    for (int r = 0; r < 3; r++) {
        int j = r * 256 + t;          // 0..767
        int pix = j / 3;
        int ch = j - pix * 3;
        unsigned id2 = s_idx[pix];
        float v;
        if (id2 != 0xFFFFFFFFu) {
            v = fmaxf(__fadd_rn(__fmul_rn(SH_C0,
                        __ldg(&shs[(size_t)id2 * 48 + ch])), 0.5f), 0.0f);
        } else {
            v = __ldg(&bg[ch]);
        }
        o_col[(size_t)p0 * 3 + j] = v;
    }

    #pragma unroll
    for (int r = 0; r < 8; r++) {
        int pix = r * 32 + pix_in_round;
        reinterpret_cast<float4*>(o_feat + ((size_t)p0 + pix) * 32)[chunk]
            = fv[r];
    }
}

// ---------------------------------------------------------------------------
// Pass 3 (tail, PDL-overlapped with resolve): re-zero the z-buffer.
// 32B per thread: NPIX*8/32 = 518400 threads = 2025 blocks of 256.
// ---------------------------------------------------------------------------
__global__ void clear_kernel() {
    pdl_wait();                     // all resolve CTAs consumed zbuf
    int t = blockIdx.x * blockDim.x + threadIdx.x;
    ulonglong2 v = make_ulonglong2(0ULL, 0ULL);
    ulonglong2* p = reinterpret_cast<ulonglong2*>(g_zbuf) + 2 * t;
    p[0] = v;
    p[1] = v;
}

// ---------------------------------------------------------------------------
// Launch. Input order (metadata): means3D, normal, means2D, feature_vector,
// shs, scales, rotations, viewmatrix, projmatrix, bg, campos
// ---------------------------------------------------------------------------
extern "C" void kernel_launch(void* const* d_in, const int* in_sizes, int n_in,
                              void* d_out, int out_size) {
    const float* means3D    = (const float*)d_in[0];
    const float* feat       = (const float*)d_in[3];
    const float* shs        = (const float*)d_in[4];
    const float* viewmatrix = (const float*)d_in[7];
    const float* projmatrix = (const float*)d_in[8];
    const float* bg         = (const float*)d_in[9];

    int n = in_sizes[0] / 3;

    cudaLaunchAttribute attrs[1];
    attrs[0].id = cudaLaunchAttributeProgrammaticStreamSerialization;
    attrs[0].val.programmaticStreamSerializationAllowed = 1;

    {
        int threads = 256;
        int quads = (n + 3) / 4;
        int blocks = (quads + threads - 1) / threads;
        cudaLaunchConfig_t cfg{};
        cfg.gridDim = dim3(blocks, 1, 1);
        cfg.blockDim = dim3(threads, 1, 1);
        cudaLaunchKernelEx(&cfg, project_kernel,
                           means3D, viewmatrix, projmatrix, n);
    }
    {
        cudaLaunchConfig_t cfg{};
        cfg.gridDim = dim3(NPIX / 256, 1, 1);   // 8100, exact
        cfg.blockDim = dim3(256, 1, 1);
        cfg.attrs = attrs;
        cfg.numAttrs = 1;
        cudaLaunchKernelEx(&cfg, resolve_kernel,
                           shs, feat, bg, (float*)d_out, n);
    }
    {
        cudaLaunchConfig_t cfg{};
        cfg.gridDim = dim3((NPIX * 8 / 32) / 256, 1, 1);  // 2025
        cfg.blockDim = dim3(256, 1, 1);
        cfg.attrs = attrs;
        cfg.numAttrs = 1;
        cudaLaunchKernelEx(&cfg, clear_kernel);
    }
}

// round 13
// speedup vs baseline: 1.0102x; 1.0102x over previous
#include <cuda_runtime.h>
#include <cstdint>

// Problem constants (match reference init_kwargs)
static constexpr int H = 1080;
static constexpr int W = 1920;
static constexpr int NPIX = H * W;           // 2,073,600 = 8100 * 256
static constexpr float ZNEAR = 0.2f;
static constexpr float SH_C0 = 0.28209479177387814f;

// Scratch z-buffer holding COMPLEMENTED keys, resolved by atomicMax.
//   stored = ~((depth_bits << 32) | idx), miss sentinel = 0.
// Cleared each call via cudaMemsetAsync (graph-capturable memset node).
__device__ unsigned long long g_zbuf[NPIX];

// PDL intrinsics (sm_90+)
__device__ __forceinline__ void pdl_wait() {
    asm volatile("griddepcontrol.wait;" ::: "memory");
}
__device__ __forceinline__ void pdl_trigger() {
    asm volatile("griddepcontrol.launch_dependents;" ::: "memory");
}

// ---------------------------------------------------------------------------
// Projection math: bit-exact per-op float32 (no FMA fusion).
// ---------------------------------------------------------------------------
struct Mats {
    float P00, P10, P20, P30;
    float P01, P11, P21, P31;
    float P03, P13, P23, P33;
    float V02, V12, V22, V32;
};

// Common tail: ndc -> pixel -> z-test -> reduction.
__device__ __forceinline__ void finish_point(float phx, float phy, float phw,
                                             float depth, int i) {
    float inv_w = __fdiv_rn(1.0f, __fadd_rn(phw, 1e-7f));
    float ndcx = __fmul_rn(phx, inv_w);
    float ndcy = __fmul_rn(phy, inv_w);
    float fx = __fsub_rn(__fmul_rn(__fmul_rn(__fadd_rn(ndcx, 1.0f),
                                             (float)W), 0.5f), 0.5f);
    float fy = __fsub_rn(__fmul_rn(__fmul_rn(__fadd_rn(ndcy, 1.0f),
                                             (float)H), 0.5f), 0.5f);

    if (!(depth > ZNEAR)) return;
    if (!(fx > -2.0f && fx < (float)(W + 1) &&
          fy > -2.0f && fy < (float)(H + 1))) return;
    int px = (int)rintf(fx);
    int py = (int)rintf(fy);
    if (px < 0 || px >= W || py < 0 || py >= H) return;

    unsigned long long key =
        ((unsigned long long)__float_as_uint(depth) << 32) | (unsigned)i;
    atomicMax(&g_zbuf[py * W + px], ~key);
}

// Generic path: full row-vector math, explicit rn ops (no fusion).
__device__ __forceinline__ void project_generic(float x, float y, float z,
                                                int i, const Mats& M) {
    float phx = __fadd_rn(__fadd_rn(__fmul_rn(x, M.P00), __fmul_rn(y, M.P10)),
                          __fadd_rn(__fmul_rn(z, M.P20), M.P30));
    float phy = __fadd_rn(__fadd_rn(__fmul_rn(x, M.P01), __fmul_rn(y, M.P11)),
                          __fadd_rn(__fmul_rn(z, M.P21), M.P31));
    float phw = __fadd_rn(__fadd_rn(__fmul_rn(x, M.P03), __fmul_rn(y, M.P13)),
                          __fadd_rn(__fmul_rn(z, M.P23), M.P33));
    float depth = __fadd_rn(__fadd_rn(__fmul_rn(x, M.V02), __fmul_rn(y, M.V12)),
                            __fadd_rn(__fmul_rn(z, M.V22), M.V32));
    finish_point(phx, phy, phw, depth, i);
}

// Fast path: valid when all off-terms are exactly 0 and P23==1, V22==1.
// Eliding exact-zero products/sums can only flip the sign of a zero result
// (-0 vs +0), which maps to the identical pixel / identical depth bits.
__device__ __forceinline__ void project_fast(float x, float y, float z,
                                             int i, const Mats& M) {
    float phx = __fmul_rn(x, M.P00);
    float phy = __fmul_rn(y, M.P11);
    finish_point(phx, phy, z, z, i);
}

__device__ __forceinline__ Mats load_mats(const float* __restrict__ viewmatrix,
                                          const float* __restrict__ projmatrix) {
    Mats M;
    M.P00 = __ldg(&projmatrix[0]);  M.P10 = __ldg(&projmatrix[4]);
    M.P20 = __ldg(&projmatrix[8]);  M.P30 = __ldg(&projmatrix[12]);
    M.P01 = __ldg(&projmatrix[1]);  M.P11 = __ldg(&projmatrix[5]);
    M.P21 = __ldg(&projmatrix[9]);  M.P31 = __ldg(&projmatrix[13]);
    M.P03 = __ldg(&projmatrix[3]);  M.P13 = __ldg(&projmatrix[7]);
    M.P23 = __ldg(&projmatrix[11]); M.P33 = __ldg(&projmatrix[15]);
    M.V02 = __ldg(&viewmatrix[2]);  M.V12 = __ldg(&viewmatrix[6]);
    M.V22 = __ldg(&viewmatrix[10]); M.V32 = __ldg(&viewmatrix[14]);
    return M;
}

__device__ __forceinline__ bool mats_are_simple(const Mats& M) {
    return M.P10 == 0.f && M.P20 == 0.f && M.P30 == 0.f &&
           M.P01 == 0.f && M.P21 == 0.f && M.P31 == 0.f &&
           M.P03 == 0.f && M.P13 == 0.f && M.P33 == 0.f && M.P23 == 1.f &&
           M.V02 == 0.f && M.V12 == 0.f && M.V32 == 0.f && M.V22 == 1.f;
}

// ---------------------------------------------------------------------------
// Pass 1: 4 points per thread; three float4 loads. Tail per-element.
// PDL: loads+math overlap the memset tail; wait only before the atomics.
// ---------------------------------------------------------------------------
__global__ void project_kernel(const float* __restrict__ means3D,
                               const float* __restrict__ viewmatrix,
                               const float* __restrict__ projmatrix,
                               int n) {
    int t = blockIdx.x * blockDim.x + threadIdx.x;
    int i0 = 4 * t;
    if (i0 >= n) { pdl_wait(); pdl_trigger(); return; }

    Mats M = load_mats(viewmatrix, projmatrix);
    bool simple = mats_are_simple(M);

    if (i0 + 4 <= n) {
        const float4* __restrict__ m4 =
            reinterpret_cast<const float4*>(means3D + 12 * (size_t)t);
        float4 a = __ldg(&m4[0]);   // x0 y0 z0 x1
        float4 b = __ldg(&m4[1]);   // y1 z1 x2 y2
        float4 c = __ldg(&m4[2]);   // z2 x3 y3 z3
        pdl_wait();                 // zbuf must be cleared before atomics
        if (simple) {
            project_fast(a.x, a.y, a.z, i0 + 0, M);
            project_fast(a.w, b.x, b.y, i0 + 1, M);
            project_fast(b.z, b.w, c.x, i0 + 2, M);
            project_fast(c.y, c.z, c.w, i0 + 3, M);
        } else {
            project_generic(a.x, a.y, a.z, i0 + 0, M);
            project_generic(a.w, b.x, b.y, i0 + 1, M);
            project_generic(b.z, b.w, c.x, i0 + 2, M);
            project_generic(c.y, c.z, c.w, i0 + 3, M);
        }
    } else {
        pdl_wait();
        for (int i = i0; i < n; i++) {
            float x = means3D[3 * i + 0];
            float y = means3D[3 * i + 1];
            float z = means3D[3 * i + 2];
            if (simple) project_fast(x, y, z, i, M);
            else        project_generic(x, y, z, i, M);
        }
    }
    pdl_trigger();                  // this CTA's zbuf updates are issued
}

// ---------------------------------------------------------------------------
// Pass 2: resolve. One block = 256 consecutive pixels (NPIX = 8100*256).
// zbuf READ-ONLY; all output stores fully coalesced; feature gathers issued
// in a batch (8 independent 128B loads in flight) before any store.
// out layout (floats): idx[NPIX] | col[NPIX*3] | depth[NPIX] | feat[NPIX*32]
// ---------------------------------------------------------------------------
__global__ __launch_bounds__(256) void resolve_kernel(
        const float* __restrict__ shs,        // stride 48 floats
        const float* __restrict__ feat,       // stride 32 floats
        const float* __restrict__ bg,
        float* __restrict__ out, int n) {
    __shared__ unsigned s_idx[256];
    __shared__ unsigned s_dep[256];

    int t = threadIdx.x;
    int p0 = blockIdx.x * 256;

    float* __restrict__ o_idx  = out;
    float* __restrict__ o_col  = out + (size_t)NPIX;
    float* __restrict__ o_dep  = out + (size_t)4 * NPIX;
    float* __restrict__ o_feat = out + (size_t)5 * NPIX;

    pdl_wait();                     // project's zbuf writes must be visible

    // Keys: 2 pixels per thread via 16B loads (first 128 threads cover 256).
    if (t < 128) {
        ulonglong2 st = __ldg(reinterpret_cast<const ulonglong2*>(
                                  &g_zbuf[p0]) + t);
        #pragma unroll
        for (int k = 0; k < 2; k++) {
            unsigned long long stored = k ? st.y : st.x;
            unsigned long long key = ~stored;
            unsigned idx = (unsigned)(key & 0xFFFFFFFFull);
            bool hit = (stored != 0ULL) && (idx < (unsigned)n);
            s_idx[2 * t + k] = hit ? idx : 0xFFFFFFFFu;
            s_dep[2 * t + k] = hit ? (unsigned)(key >> 32) : 0u;
        }
    }
    __syncthreads();

    {
        unsigned id = s_idx[t];
        bool hit = id != 0xFFFFFFFFu;
        o_idx[p0 + t] = hit ? (float)id : -1.0f;
        o_dep[p0 + t] = __uint_as_float(s_dep[t]);
    }

    // Features: batch all 8 gather loads (independent, in flight together),
    // then all 8 coalesced stores. 8 threads per pixel, one float4 chunk.
    int pix_in_round = t >> 3;        // 0..31
    int chunk = t & 7;                // 0..7
    float4 fv[8];
    #pragma unroll
    for (int r = 0; r < 8; r++) {
        int pix = r * 32 + pix_in_round;      // 0..255
        unsigned id2 = s_idx[pix];
        fv[r] = (id2 != 0xFFFFFFFFu)
            ? __ldg(&reinterpret_cast<const float4*>(
                        feat + (size_t)id2 * 32)[chunk])
            : make_float4(0.f, 0.f, 0.f, 0.f);
    }

    // Color: 3 rounds of 256 contiguous floats (overlaps with feat loads).
    #pragma unroll
    for (int r = 0; r < 3; r++) {
        int j = r * 256 + t;          // 0..767
        int pix = j / 3;
        int ch = j - pix * 3;
        unsigned id2 = s_idx[pix];
        float v;
        if (id2 != 0xFFFFFFFFu) {
            v = fmaxf(__fadd_rn(__fmul_rn(SH_C0,
                        __ldg(&shs[(size_t)id2 * 48 + ch])), 0.5f), 0.0f);
        } else {
            v = __ldg(&bg[ch]);
        }
        o_col[(size_t)p0 * 3 + j] = v;
    }

    #pragma unroll
    for (int r = 0; r < 8; r++) {
        int pix = r * 32 + pix_in_round;
        reinterpret_cast<float4*>(o_feat + ((size_t)p0 + pix) * 32)[chunk]
            = fv[r];
    }
}

// ---------------------------------------------------------------------------
// Launch. Input order (metadata): means3D, normal, means2D, feature_vector,
// shs, scales, rotations, viewmatrix, projmatrix, bg, campos
// ---------------------------------------------------------------------------
extern "C" void kernel_launch(void* const* d_in, const int* in_sizes, int n_in,
                              void* d_out, int out_size) {
    const float* means3D    = (const float*)d_in[0];
    const float* feat       = (const float*)d_in[3];
    const float* shs        = (const float*)d_in[4];
    const float* viewmatrix = (const float*)d_in[7];
    const float* projmatrix = (const float*)d_in[8];
    const float* bg         = (const float*)d_in[9];

    int n = in_sizes[0] / 3;

    // Clear the z-buffer with a memset node (graph-capturable, full fill BW).
    void* zbuf_ptr = nullptr;
    cudaGetSymbolAddress(&zbuf_ptr, g_zbuf);
    cudaMemsetAsync(zbuf_ptr, 0, (size_t)NPIX * sizeof(unsigned long long), 0);

    cudaLaunchAttribute attrs[1];
    attrs[0].id = cudaLaunchAttributeProgrammaticStreamSerialization;
    attrs[0].val.programmaticStreamSerializationAllowed = 1;

    {
        int threads = 256;
        int quads = (n + 3) / 4;
        int blocks = (quads + threads - 1) / threads;
        cudaLaunchConfig_t cfg{};
        cfg.gridDim = dim3(blocks, 1, 1);
        cfg.blockDim = dim3(threads, 1, 1);
        cfg.attrs = attrs;
        cfg.numAttrs = 1;
        cudaLaunchKernelEx(&cfg, project_kernel,
                           means3D, viewmatrix, projmatrix, n);
    }
    {
        cudaLaunchConfig_t cfg{};
        cfg.gridDim = dim3(NPIX / 256, 1, 1);   // 8100, exact
        cfg.blockDim = dim3(256, 1, 1);
        cfg.attrs = attrs;
        cfg.numAttrs = 1;
        cudaLaunchKernelEx(&cfg, resolve_kernel,
                           shs, feat, bg, (float*)d_out, n);
    }
}

// round 14
// speedup vs baseline: 1.0240x; 1.0137x over previous
#include <cuda_runtime.h>
#include <cstdint>

// Problem constants (match reference init_kwargs)
static constexpr int H = 1080;
static constexpr int W = 1920;
static constexpr int NPIX = H * W;           // 2,073,600 = 8100 * 256
static constexpr float ZNEAR = 0.2f;
static constexpr float SH_C0 = 0.28209479177387814f;

// Scratch z-buffer holding COMPLEMENTED keys, resolved by atomicMax.
//   stored = ~((depth_bits << 32) | idx), miss sentinel = 0.
// Cleared each call via cudaMemsetAsync (graph-capturable memset node).
__device__ unsigned long long g_zbuf[NPIX];

// PDL intrinsics (sm_90+)
__device__ __forceinline__ void pdl_wait() {
    asm volatile("griddepcontrol.wait;" ::: "memory");
}
__device__ __forceinline__ void pdl_trigger() {
    asm volatile("griddepcontrol.launch_dependents;" ::: "memory");
}

// ---------------------------------------------------------------------------
// Projection math: bit-exact per-op float32 (no FMA fusion).
// ---------------------------------------------------------------------------
struct Mats {
    float P00, P10, P20, P30;
    float P01, P11, P21, P31;
    float P03, P13, P23, P33;
    float V02, V12, V22, V32;
};

// Common tail: ndc -> pixel -> z-test -> reduction.
__device__ __forceinline__ void finish_point(float phx, float phy, float phw,
                                             float depth, int i) {
    float inv_w = __fdiv_rn(1.0f, __fadd_rn(phw, 1e-7f));
    float ndcx = __fmul_rn(phx, inv_w);
    float ndcy = __fmul_rn(phy, inv_w);
    float fx = __fsub_rn(__fmul_rn(__fmul_rn(__fadd_rn(ndcx, 1.0f),
                                             (float)W), 0.5f), 0.5f);
    float fy = __fsub_rn(__fmul_rn(__fmul_rn(__fadd_rn(ndcy, 1.0f),
                                             (float)H), 0.5f), 0.5f);

    if (!(depth > ZNEAR)) return;
    if (!(fx > -2.0f && fx < (float)(W + 1) &&
          fy > -2.0f && fy < (float)(H + 1))) return;
    int px = (int)rintf(fx);
    int py = (int)rintf(fy);
    if (px < 0 || px >= W || py < 0 || py >= H) return;

    unsigned long long key =
        ((unsigned long long)__float_as_uint(depth) << 32) | (unsigned)i;
    atomicMax(&g_zbuf[py * W + px], ~key);
}

// Generic path: full row-vector math, explicit rn ops (no fusion).
__device__ __forceinline__ void project_generic(float x, float y, float z,
                                                int i, const Mats& M) {
    float phx = __fadd_rn(__fadd_rn(__fmul_rn(x, M.P00), __fmul_rn(y, M.P10)),
                          __fadd_rn(__fmul_rn(z, M.P20), M.P30));
    float phy = __fadd_rn(__fadd_rn(__fmul_rn(x, M.P01), __fmul_rn(y, M.P11)),
                          __fadd_rn(__fmul_rn(z, M.P21), M.P31));
    float phw = __fadd_rn(__fadd_rn(__fmul_rn(x, M.P03), __fmul_rn(y, M.P13)),
                          __fadd_rn(__fmul_rn(z, M.P23), M.P33));
    float depth = __fadd_rn(__fadd_rn(__fmul_rn(x, M.V02), __fmul_rn(y, M.V12)),
                            __fadd_rn(__fmul_rn(z, M.V22), M.V32));
    finish_point(phx, phy, phw, depth, i);
}

// Fast path: valid when all off-terms are exactly 0 and P23==1, V22==1.
// Eliding exact-zero products/sums can only flip the sign of a zero result
// (-0 vs +0), which maps to the identical pixel / identical depth bits.
__device__ __forceinline__ void project_fast(float x, float y, float z,
                                             int i, const Mats& M) {
    float phx = __fmul_rn(x, M.P00);
    float phy = __fmul_rn(y, M.P11);
    finish_point(phx, phy, z, z, i);
}

__device__ __forceinline__ Mats load_mats(const float* __restrict__ viewmatrix,
                                          const float* __restrict__ projmatrix) {
    Mats M;
    M.P00 = __ldg(&projmatrix[0]);  M.P10 = __ldg(&projmatrix[4]);
    M.P20 = __ldg(&projmatrix[8]);  M.P30 = __ldg(&projmatrix[12]);
    M.P01 = __ldg(&projmatrix[1]);  M.P11 = __ldg(&projmatrix[5]);
    M.P21 = __ldg(&projmatrix[9]);  M.P31 = __ldg(&projmatrix[13]);
    M.P03 = __ldg(&projmatrix[3]);  M.P13 = __ldg(&projmatrix[7]);
    M.P23 = __ldg(&projmatrix[11]); M.P33 = __ldg(&projmatrix[15]);
    M.V02 = __ldg(&viewmatrix[2]);  M.V12 = __ldg(&viewmatrix[6]);
    M.V22 = __ldg(&viewmatrix[10]); M.V32 = __ldg(&viewmatrix[14]);
    return M;
}

__device__ __forceinline__ bool mats_are_simple(const Mats& M) {
    return M.P10 == 0.f && M.P20 == 0.f && M.P30 == 0.f &&
           M.P01 == 0.f && M.P21 == 0.f && M.P31 == 0.f &&
           M.P03 == 0.f && M.P13 == 0.f && M.P33 == 0.f && M.P23 == 1.f &&
           M.V02 == 0.f && M.V12 == 0.f && M.V32 == 0.f && M.V22 == 1.f;
}

// ---------------------------------------------------------------------------
// Pass 1: 2 points per thread (maximize warps in flight -- project is
// latency-bound on load+atomic chains, not instruction-bound).
// means3D pair loaded as three float2 (8B-aligned at 24B*t).
// PDL: loads overlap the memset tail; wait only before the atomics.
// ---------------------------------------------------------------------------
__global__ void project_kernel(const float* __restrict__ means3D,
                               const float* __restrict__ viewmatrix,
                               const float* __restrict__ projmatrix,
                               int n) {
    int t = blockIdx.x * blockDim.x + threadIdx.x;
    int i0 = 2 * t;
    if (i0 >= n) { pdl_wait(); pdl_trigger(); return; }

    Mats M = load_mats(viewmatrix, projmatrix);
    bool simple = mats_are_simple(M);

    if (i0 + 2 <= n) {
        const float2* __restrict__ m2 =
            reinterpret_cast<const float2*>(means3D + 6 * (size_t)t);
        float2 a = __ldg(&m2[0]);   // x0 y0
        float2 b = __ldg(&m2[1]);   // z0 x1
        float2 c = __ldg(&m2[2]);   // y1 z1
        pdl_wait();                 // zbuf must be cleared before atomics
        if (simple) {
            project_fast(a.x, a.y, b.x, i0 + 0, M);
            project_fast(b.y, c.x, c.y, i0 + 1, M);
        } else {
            project_generic(a.x, a.y, b.x, i0 + 0, M);
            project_generic(b.y, c.x, c.y, i0 + 1, M);
        }
    } else {
        pdl_wait();
        for (int i = i0; i < n; i++) {
            float x = means3D[3 * i + 0];
            float y = means3D[3 * i + 1];
            float z = means3D[3 * i + 2];
            if (simple) project_fast(x, y, z, i, M);
            else        project_generic(x, y, z, i, M);
        }
    }
    pdl_trigger();                  // this CTA's zbuf updates are issued
}

// ---------------------------------------------------------------------------
// Pass 2: resolve. One block = 256 consecutive pixels (NPIX = 8100*256).
// zbuf READ-ONLY; all output stores fully coalesced; feature gathers issued
// in a batch (8 independent 128B loads in flight) before any store.
// out layout (floats): idx[NPIX] | col[NPIX*3] | depth[NPIX] | feat[NPIX*32]
// ---------------------------------------------------------------------------
__global__ __launch_bounds__(256) void resolve_kernel(
        const float* __restrict__ shs,        // stride 48 floats
        const float* __restrict__ feat,       // stride 32 floats
        const float* __restrict__ bg,
        float* __restrict__ out, int n) {
    __shared__ unsigned s_idx[256];
    __shared__ unsigned s_dep[256];

    int t = threadIdx.x;
    int p0 = blockIdx.x * 256;

    float* __restrict__ o_idx  = out;
    float* __restrict__ o_col  = out + (size_t)NPIX;
    float* __restrict__ o_dep  = out + (size_t)4 * NPIX;
    float* __restrict__ o_feat = out + (size_t)5 * NPIX;

    pdl_wait();                     // project's zbuf writes must be visible

    // Keys: 2 pixels per thread via 16B loads (first 128 threads cover 256).
    if (t < 128) {
        ulonglong2 st = __ldg(reinterpret_cast<const ulonglong2*>(
                                  &g_zbuf[p0]) + t);
        #pragma unroll
        for (int k = 0; k < 2; k++) {
            unsigned long long stored = k ? st.y : st.x;
            unsigned long long key = ~stored;
            unsigned idx = (unsigned)(key & 0xFFFFFFFFull);
            bool hit = (stored != 0ULL) && (idx < (unsigned)n);
            s_idx[2 * t + k] = hit ? idx : 0xFFFFFFFFu;
            s_dep[2 * t + k] = hit ? (unsigned)(key >> 32) : 0u;
        }
    }
    __syncthreads();

    {
        unsigned id = s_idx[t];
        bool hit = id != 0xFFFFFFFFu;
        o_idx[p0 + t] = hit ? (float)id : -1.0f;
        o_dep[p0 + t] = __uint_as_float(s_dep[t]);
    }

    // Features: batch all 8 gather loads (independent, in flight together),
    // then all 8 coalesced stores. 8 threads per pixel, one float4 chunk.
    int pix_in_round = t >> 3;        // 0..31
    int chunk = t & 7;                // 0..7
    float4 fv[8];
    #pragma unroll
    for (int r = 0; r < 8; r++) {
        int pix = r * 32 + pix_in_round;      // 0..255
        unsigned id2 = s_idx[pix];
        fv[r] = (id2 != 0xFFFFFFFFu)
            ? __ldg(&reinterpret_cast<const float4*>(
                        feat + (size_t)id2 * 32)[chunk])
            : make_float4(0.f, 0.f, 0.f, 0.f);
    }

    // Color: 3 rounds of 256 contiguous floats (overlaps with feat loads).
    #pragma unroll
    for (int r = 0; r < 3; r++) {
        int j = r * 256 + t;          // 0..767
        int pix = j / 3;
        int ch = j - pix * 3;
        unsigned id2 = s_idx[pix];
        float v;
        if (id2 != 0xFFFFFFFFu) {
            v = fmaxf(__fadd_rn(__fmul_rn(SH_C0,
                        __ldg(&shs[(size_t)id2 * 48 + ch])), 0.5f), 0.0f);
        } else {
            v = __ldg(&bg[ch]);
        }
        o_col[(size_t)p0 * 3 + j] = v;
    }

    #pragma unroll
    for (int r = 0; r < 8; r++) {
        int pix = r * 32 + pix_in_round;
        reinterpret_cast<float4*>(o_feat + ((size_t)p0 + pix) * 32)[chunk]
            = fv[r];
    }
}

// ---------------------------------------------------------------------------
// Launch. Input order (metadata): means3D, normal, means2D, feature_vector,
// shs, scales, rotations, viewmatrix, projmatrix, bg, campos
// ---------------------------------------------------------------------------
extern "C" void kernel_launch(void* const* d_in, const int* in_sizes, int n_in,
                              void* d_out, int out_size) {
    const float* means3D    = (const float*)d_in[0];
    const float* feat       = (const float*)d_in[3];
    const float* shs        = (const float*)d_in[4];
    const float* viewmatrix = (const float*)d_in[7];
    const float* projmatrix = (const float*)d_in[8];
    const float* bg         = (const float*)d_in[9];

    int n = in_sizes[0] / 3;

    // Clear the z-buffer with a memset node (graph-capturable, full fill BW).
    void* zbuf_ptr = nullptr;
    cudaGetSymbolAddress(&zbuf_ptr, g_zbuf);
    cudaMemsetAsync(zbuf_ptr, 0, (size_t)NPIX * sizeof(unsigned long long), 0);

    cudaLaunchAttribute attrs[1];
    attrs[0].id = cudaLaunchAttributeProgrammaticStreamSerialization;
    attrs[0].val.programmaticStreamSerializationAllowed = 1;

    {
        int threads = 256;
        int pairs = (n + 1) / 2;
        int blocks = (pairs + threads - 1) / threads;
        cudaLaunchConfig_t cfg{};
        cfg.gridDim = dim3(blocks, 1, 1);
        cfg.blockDim = dim3(threads, 1, 1);
        cfg.attrs = attrs;
        cfg.numAttrs = 1;
        cudaLaunchKernelEx(&cfg, project_kernel,
                           means3D, viewmatrix, projmatrix, n);
    }
    {
        cudaLaunchConfig_t cfg{};
        cfg.gridDim = dim3(NPIX / 256, 1, 1);   // 8100, exact
        cfg.blockDim = dim3(256, 1, 1);
        cfg.attrs = attrs;
        cfg.numAttrs = 1;
        cudaLaunchKernelEx(&cfg, resolve_kernel,
                           shs, feat, bg, (float*)d_out, n);
    }
}

// round 15
// speedup vs baseline: 1.0252x; 1.0011x over previous
#include <cuda_runtime.h>
#include <cstdint>

// Problem constants (match reference init_kwargs)
static constexpr int H = 1080;
static constexpr int W = 1920;
static constexpr int NPIX = H * W;           // 2,073,600 = 8100 * 256
static constexpr float ZNEAR = 0.2f;
static constexpr float SH_C0 = 0.28209479177387814f;

// Scratch z-buffer holding COMPLEMENTED keys, resolved by atomicMax.
//   stored = ~((depth_bits << 32) | idx), miss sentinel = 0.
// Cleared each call via cudaMemsetAsync (graph-capturable memset node).
__device__ unsigned long long g_zbuf[NPIX];

// PDL intrinsics (sm_90+)
__device__ __forceinline__ void pdl_wait() {
    asm volatile("griddepcontrol.wait;" ::: "memory");
}
__device__ __forceinline__ void pdl_trigger() {
    asm volatile("griddepcontrol.launch_dependents;" ::: "memory");
}

// ---------------------------------------------------------------------------
// Projection math: bit-exact per-op float32 (no FMA fusion).
// ---------------------------------------------------------------------------
struct Mats {
    float P00, P10, P20, P30;
    float P01, P11, P21, P31;
    float P03, P13, P23, P33;
    float V02, V12, V22, V32;
};

// Common tail: ndc -> pixel -> z-test -> reduction.
__device__ __forceinline__ void finish_point(float phx, float phy, float phw,
                                             float depth, int i) {
    float inv_w = __fdiv_rn(1.0f, __fadd_rn(phw, 1e-7f));
    float ndcx = __fmul_rn(phx, inv_w);
    float ndcy = __fmul_rn(phy, inv_w);
    float fx = __fsub_rn(__fmul_rn(__fmul_rn(__fadd_rn(ndcx, 1.0f),
                                             (float)W), 0.5f), 0.5f);
    float fy = __fsub_rn(__fmul_rn(__fmul_rn(__fadd_rn(ndcy, 1.0f),
                                             (float)H), 0.5f), 0.5f);

    if (!(depth > ZNEAR)) return;
    if (!(fx > -2.0f && fx < (float)(W + 1) &&
          fy > -2.0f && fy < (float)(H + 1))) return;
    int px = (int)rintf(fx);
    int py = (int)rintf(fy);
    if (px < 0 || px >= W || py < 0 || py >= H) return;

    unsigned long long key =
        ((unsigned long long)__float_as_uint(depth) << 32) | (unsigned)i;
    atomicMax(&g_zbuf[py * W + px], ~key);
}

// Generic path: full row-vector math, explicit rn ops (no fusion).
__device__ __forceinline__ void project_generic(float x, float y, float z,
                                                int i, const Mats& M) {
    float phx = __fadd_rn(__fadd_rn(__fmul_rn(x, M.P00), __fmul_rn(y, M.P10)),
                          __fadd_rn(__fmul_rn(z, M.P20), M.P30));
    float phy = __fadd_rn(__fadd_rn(__fmul_rn(x, M.P01), __fmul_rn(y, M.P11)),
                          __fadd_rn(__fmul_rn(z, M.P21), M.P31));
    float phw = __fadd_rn(__fadd_rn(__fmul_rn(x, M.P03), __fmul_rn(y, M.P13)),
                          __fadd_rn(__fmul_rn(z, M.P23), M.P33));
    float depth = __fadd_rn(__fadd_rn(__fmul_rn(x, M.V02), __fmul_rn(y, M.V12)),
                            __fadd_rn(__fmul_rn(z, M.V22), M.V32));
    finish_point(phx, phy, phw, depth, i);
}

// Fast path: valid when all off-terms are exactly 0 and P23==1, V22==1.
// Eliding exact-zero products/sums can only flip the sign of a zero result
// (-0 vs +0), which maps to the identical pixel / identical depth bits.
__device__ __forceinline__ void project_fast(float x, float y, float z,
                                             int i, const Mats& M) {
    float phx = __fmul_rn(x, M.P00);
    float phy = __fmul_rn(y, M.P11);
    finish_point(phx, phy, z, z, i);
}

__device__ __forceinline__ Mats load_mats(const float* __restrict__ viewmatrix,
                                          const float* __restrict__ projmatrix) {
    Mats M;
    M.P00 = __ldg(&projmatrix[0]);  M.P10 = __ldg(&projmatrix[4]);
    M.P20 = __ldg(&projmatrix[8]);  M.P30 = __ldg(&projmatrix[12]);
    M.P01 = __ldg(&projmatrix[1]);  M.P11 = __ldg(&projmatrix[5]);
    M.P21 = __ldg(&projmatrix[9]);  M.P31 = __ldg(&projmatrix[13]);
    M.P03 = __ldg(&projmatrix[3]);  M.P13 = __ldg(&projmatrix[7]);
    M.P23 = __ldg(&projmatrix[11]); M.P33 = __ldg(&projmatrix[15]);
    M.V02 = __ldg(&viewmatrix[2]);  M.V12 = __ldg(&viewmatrix[6]);
    M.V22 = __ldg(&viewmatrix[10]); M.V32 = __ldg(&viewmatrix[14]);
    return M;
}

__device__ __forceinline__ bool mats_are_simple(const Mats& M) {
    return M.P10 == 0.f && M.P20 == 0.f && M.P30 == 0.f &&
           M.P01 == 0.f && M.P21 == 0.f && M.P31 == 0.f &&
           M.P03 == 0.f && M.P13 == 0.f && M.P33 == 0.f && M.P23 == 1.f &&
           M.V02 == 0.f && M.V12 == 0.f && M.V32 == 0.f && M.V22 == 1.f;
}

// ---------------------------------------------------------------------------
// Pass 1: ONE point per thread (maximize warps in flight -- project is
// latency-bound on the load->divide->atomic chain, not instruction-bound).
// Warp reads 384B contiguous (3 coalesced 32-bit loads per thread).
// PDL: loads overlap the memset tail; wait only before the atomic.
// ---------------------------------------------------------------------------
__global__ void project_kernel(const float* __restrict__ means3D,
                               const float* __restrict__ viewmatrix,
                               const float* __restrict__ projmatrix,
                               int n) {
    int i = blockIdx.x * blockDim.x + threadIdx.x;
    if (i >= n) { pdl_wait(); pdl_trigger(); return; }

    Mats M = load_mats(viewmatrix, projmatrix);
    bool simple = mats_are_simple(M);

    float x = __ldg(&means3D[3 * i + 0]);
    float y = __ldg(&means3D[3 * i + 1]);
    float z = __ldg(&means3D[3 * i + 2]);

    pdl_wait();                     // zbuf must be cleared before atomics
    if (simple) project_fast(x, y, z, i, M);
    else        project_generic(x, y, z, i, M);
    pdl_trigger();                  // this CTA's zbuf updates are issued
}

// ---------------------------------------------------------------------------
// Pass 2: resolve. One block = 256 consecutive pixels (NPIX = 8100*256).
// zbuf READ-ONLY; all output stores fully coalesced; feature gathers issued
// in a batch (8 independent 128B loads in flight) before any store.
// out layout (floats): idx[NPIX] | col[NPIX*3] | depth[NPIX] | feat[NPIX*32]
// ---------------------------------------------------------------------------
__global__ __launch_bounds__(256) void resolve_kernel(
        const float* __restrict__ shs,        // stride 48 floats
        const float* __restrict__ feat,       // stride 32 floats
        const float* __restrict__ bg,
        float* __restrict__ out, int n) {
    __shared__ unsigned s_idx[256];
    __shared__ unsigned s_dep[256];

    int t = threadIdx.x;
    int p0 = blockIdx.x * 256;

    float* __restrict__ o_idx  = out;
    float* __restrict__ o_col  = out + (size_t)NPIX;
    float* __restrict__ o_dep  = out + (size_t)4 * NPIX;
    float* __restrict__ o_feat = out + (size_t)5 * NPIX;

    pdl_wait();                     // project's zbuf writes must be visible

    // Keys: 2 pixels per thread via 16B loads (first 128 threads cover 256).
    if (t < 128) {
        ulonglong2 st = __ldg(reinterpret_cast<const ulonglong2*>(
                                  &g_zbuf[p0]) + t);
        #pragma unroll
        for (int k = 0; k < 2; k++) {
            unsigned long long stored = k ? st.y : st.x;
            unsigned long long key = ~stored;
            unsigned idx = (unsigned)(key & 0xFFFFFFFFull);
            bool hit = (stored != 0ULL) && (idx < (unsigned)n);
            s_idx[2 * t + k] = hit ? idx : 0xFFFFFFFFu;
            s_dep[2 * t + k] = hit ? (unsigned)(key >> 32) : 0u;
        }
    }
    __syncthreads();

    {
        unsigned id = s_idx[t];
        bool hit = id != 0xFFFFFFFFu;
        o_idx[p0 + t] = hit ? (float)id : -1.0f;
        o_dep[p0 + t] = __uint_as_float(s_dep[t]);
    }

    // Features: batch all 8 gather loads (independent, in flight together),
    // then all 8 coalesced stores. 8 threads per pixel, one float4 chunk.
    int pix_in_round = t >> 3;        // 0..31
    int chunk = t & 7;                // 0..7
    float4 fv[8];
    #pragma unroll
    for (int r = 0; r < 8; r++) {
        int pix = r * 32 + pix_in_round;      // 0..255
        unsigned id2 = s_idx[pix];
        fv[r] = (id2 != 0xFFFFFFFFu)
            ? __ldg(&reinterpret_cast<const float4*>(
                        feat + (size_t)id2 * 32)[chunk])
            : make_float4(0.f, 0.f, 0.f, 0.f);
    }

    // Color: 3 rounds of 256 contiguous floats (overlaps with feat loads).
    #pragma unroll
    for (int r = 0; r < 3; r++) {
        int j = r * 256 + t;          // 0..767
        int pix = j / 3;
        int ch = j - pix * 3;
        unsigned id2 = s_idx[pix];
        float v;
        if (id2 != 0xFFFFFFFFu) {
            v = fmaxf(__fadd_rn(__fmul_rn(SH_C0,
                        __ldg(&shs[(size_t)id2 * 48 + ch])), 0.5f), 0.0f);
        } else {
            v = __ldg(&bg[ch]);
        }
        o_col[(size_t)p0 * 3 + j] = v;
    }

    #pragma unroll
    for (int r = 0; r < 8; r++) {
        int pix = r * 32 + pix_in_round;
        reinterpret_cast<float4*>(o_feat + ((size_t)p0 + pix) * 32)[chunk]
            = fv[r];
    }
}

// ---------------------------------------------------------------------------
// Launch. Input order (metadata): means3D, normal, means2D, feature_vector,
// shs, scales, rotations, viewmatrix, projmatrix, bg, campos
// ---------------------------------------------------------------------------
extern "C" void kernel_launch(void* const* d_in, const int* in_sizes, int n_in,
                              void* d_out, int out_size) {
    const float* means3D    = (const float*)d_in[0];
    const float* feat       = (const float*)d_in[3];
    const float* shs        = (const float*)d_in[4];
    const float* viewmatrix = (const float*)d_in[7];
    const float* projmatrix = (const float*)d_in[8];
    const float* bg         = (const float*)d_in[9];

    int n = in_sizes[0] / 3;

    // Clear the z-buffer with a memset node (graph-capturable, full fill BW).
    void* zbuf_ptr = nullptr;
    cudaGetSymbolAddress(&zbuf_ptr, g_zbuf);
    cudaMemsetAsync(zbuf_ptr, 0, (size_t)NPIX * sizeof(unsigned long long), 0);

    cudaLaunchAttribute attrs[1];
    attrs[0].id = cudaLaunchAttributeProgrammaticStreamSerialization;
    attrs[0].val.programmaticStreamSerializationAllowed = 1;

    {
        int threads = 256;
        int blocks = (n + threads - 1) / threads;
        cudaLaunchConfig_t cfg{};
        cfg.gridDim = dim3(blocks, 1, 1);
        cfg.blockDim = dim3(threads, 1, 1);
        cfg.attrs = attrs;
        cfg.numAttrs = 1;
        cudaLaunchKernelEx(&cfg, project_kernel,
                           means3D, viewmatrix, projmatrix, n);
    }
    {
        cudaLaunchConfig_t cfg{};
        cfg.gridDim = dim3(NPIX / 256, 1, 1);   // 8100, exact
        cfg.blockDim = dim3(256, 1, 1);
        cfg.attrs = attrs;
        cfg.numAttrs = 1;
        cudaLaunchKernelEx(&cfg, resolve_kernel,
                           shs, feat, bg, (float*)d_out, n);
    }
}